// round 1
// baseline (speedup 1.0000x reference)
#include <cuda_runtime.h>
#include <math.h>

#define BDIM   16
#define TDIM   2048
#define FDIM   128
#define LDIM   16
#define LIB    1016
#define NROWS  (BDIM*TDIM)          // 32768

// output offsets (floats)
#define Y_OFF   ((size_t)0)
#define X_OFF   ((size_t)524288)
#define Z_OFF   ((size_t)4718592)
#define J_OFF   ((size_t)5242880)
#define WS_OFF  ((size_t)72351744)
#define WD_OFF  ((size_t)72368000)

// scratch for hilbert outputs (abs / angle), layout [B,T,L]
__device__ float g_amp[NROWS * LDIM];
__device__ float g_ang[NROWS * LDIM];

// ---------------------------------------------------------------------------
// K1: encoder  z = x @ W_enc^T + b_enc   (also writes z into the output blob)
// grid 256 x 128, one thread per (b,t) row
// ---------------------------------------------------------------------------
__global__ __launch_bounds__(128) void encoder_kernel(
    const float* __restrict__ x, const float* __restrict__ W_enc,
    const float* __restrict__ b_enc, float* __restrict__ z_out)
{
    __shared__ float4 sW[512];   // W_enc [16][128] as float4[16][32]
    __shared__ float  sb[16];
    const int tid = threadIdx.x;
    for (int i = tid; i < 512; i += 128) sW[i] = ((const float4*)W_enc)[i];
    if (tid < 16) sb[tid] = b_enc[tid];
    __syncthreads();

    const int row = blockIdx.x * 128 + tid;
    const float4* xr = (const float4*)(x + (size_t)row * FDIM);

    float acc[16];
#pragma unroll
    for (int l = 0; l < 16; l++) acc[l] = sb[l];

#pragma unroll 4
    for (int c = 0; c < 32; c++) {
        float4 xv = xr[c];
#pragma unroll
        for (int l = 0; l < 16; l++) {
            float4 wv = sW[l * 32 + c];
            acc[l] = fmaf(xv.x, wv.x, acc[l]);
            acc[l] = fmaf(xv.y, wv.y, acc[l]);
            acc[l] = fmaf(xv.z, wv.z, acc[l]);
            acc[l] = fmaf(xv.w, wv.w, acc[l]);
        }
    }
    float4* zo = (float4*)(z_out + (size_t)row * LDIM);
    zo[0] = make_float4(acc[0],  acc[1],  acc[2],  acc[3]);
    zo[1] = make_float4(acc[4],  acc[5],  acc[6],  acc[7]);
    zo[2] = make_float4(acc[8],  acc[9],  acc[10], acc[11]);
    zo[3] = make_float4(acc[12], acc[13], acc[14], acc[15]);
}

// ---------------------------------------------------------------------------
// K2: Hilbert transform per (b, latent). One block per sequence of length 2048.
// Radix-2 Stockham FFT in shared memory: fwd FFT -> H filter -> inv FFT ->
// amp/angle.  H[0]=0, H[1..1023]=2, H[1024..2047]=0  (matches reference).
// grid 256 x 256
// ---------------------------------------------------------------------------
__global__ __launch_bounds__(256) void hilbert_kernel(const float* __restrict__ z)
{
    __shared__ float2 bufA[2048];
    __shared__ float2 bufB[2048];

    const int b   = blockIdx.x >> 4;
    const int lat = blockIdx.x & 15;
    const int tid = threadIdx.x;

    const float* zp = z + ((size_t)b * TDIM) * LDIM + lat;
    for (int t = tid; t < 2048; t += 256)
        bufA[t] = make_float2(zp[(size_t)t * LDIM], 0.0f);
    __syncthreads();

    float2* src = bufA;
    float2* dst = bufB;

    // forward FFT (sign -1)
    for (int p = 0; p < 11; p++) {
        const int   len  = 1 << p;
        const float coef = -3.14159265358979323846f / (float)len;
        for (int j = tid; j < 1024; j += 256) {
            const int k = j & (len - 1);
            float2 a  = src[j];
            float2 bb = src[j + 1024];
            float s, c;
            __sincosf(coef * (float)k, &s, &c);
            float2 wb = make_float2(c * bb.x - s * bb.y, c * bb.y + s * bb.x);
            const int base = 2 * (j - k) + k;
            dst[base]       = make_float2(a.x + wb.x, a.y + wb.y);
            dst[base + len] = make_float2(a.x - wb.x, a.y - wb.y);
        }
        __syncthreads();
        float2* t = src; src = dst; dst = t;
    }

    // apply hilbert filter
    for (int t = tid; t < 2048; t += 256) {
        float h = (t >= 1 && t < 1024) ? 2.0f : 0.0f;
        src[t].x *= h;
        src[t].y *= h;
    }
    __syncthreads();

    // inverse FFT (sign +1), scale 1/N at the end
    for (int p = 0; p < 11; p++) {
        const int   len  = 1 << p;
        const float coef = 3.14159265358979323846f / (float)len;
        for (int j = tid; j < 1024; j += 256) {
            const int k = j & (len - 1);
            float2 a  = src[j];
            float2 bb = src[j + 1024];
            float s, c;
            __sincosf(coef * (float)k, &s, &c);
            float2 wb = make_float2(c * bb.x - s * bb.y, c * bb.y + s * bb.x);
            const int base = 2 * (j - k) + k;
            dst[base]       = make_float2(a.x + wb.x, a.y + wb.y);
            dst[base + len] = make_float2(a.x - wb.x, a.y - wb.y);
        }
        __syncthreads();
        float2* t = src; src = dst; dst = t;
    }

    const float scale = 1.0f / 2048.0f;
    const size_t obase = ((size_t)b * TDIM) * LDIM + lat;
    for (int t = tid; t < 2048; t += 256) {
        float re = src[t].x * scale;
        float im = src[t].y * scale;
        g_amp[obase + (size_t)t * LDIM] = sqrtf(re * re + im * im);
        g_ang[obase + (size_t)t * LDIM] = atan2f(im, re);
    }
}

// ---------------------------------------------------------------------------
// K3: fused role-partitioned kernel.
//   role Y (256 blocks): y_hat = theta @ W_sindy^T + b_sindy  (theta on the fly)
//   role X (256 blocks): x_hat = z @ W_dec^T + b_dec
//   role J (1792 blocks): jac = broadcast W_enc tile (268 MB streaming stores)
//   role C (1 block): copy W_sindy, W_dec into output
// Roles interleaved with period 9 (1 Y : 1 X : 7 J) so DRAM-bound and
// FMA-bound blocks overlap in every wave.
// dynamic smem: 90112 B (W_sindy transposed 65024 + per-thread feats 25088)
// ---------------------------------------------------------------------------
#define FEAT(val) do {                                                  \
    float fv = (val);                                                   \
    float4 w0 = w[0], w1 = w[1], w2 = w[2], w3 = w[3]; w += 4;          \
    a0.x = fmaf(fv, w0.x, a0.x); a0.y = fmaf(fv, w0.y, a0.y);           \
    a0.z = fmaf(fv, w0.z, a0.z); a0.w = fmaf(fv, w0.w, a0.w);           \
    a1.x = fmaf(fv, w1.x, a1.x); a1.y = fmaf(fv, w1.y, a1.y);           \
    a1.z = fmaf(fv, w1.z, a1.z); a1.w = fmaf(fv, w1.w, a1.w);           \
    a2.x = fmaf(fv, w2.x, a2.x); a2.y = fmaf(fv, w2.y, a2.y);           \
    a2.z = fmaf(fv, w2.z, a2.z); a2.w = fmaf(fv, w2.w, a2.w);           \
    a3.x = fmaf(fv, w3.x, a3.x); a3.y = fmaf(fv, w3.y, a3.y);           \
    a3.z = fmaf(fv, w3.z, a3.z); a3.w = fmaf(fv, w3.w, a3.w);           \
} while (0)

__global__ __launch_bounds__(128) void fused_kernel(
    const float* __restrict__ W_enc,
    const float* __restrict__ W_dec,  const float* __restrict__ b_dec,
    const float* __restrict__ W_sindy, const float* __restrict__ b_sindy,
    const float* __restrict__ z,       // z region of output blob
    float* __restrict__ out)
{
    extern __shared__ float smem[];
    const int tid = threadIdx.x;
    const int bb  = blockIdx.x;

    if (bb == 2304) {
        // ---- role C: copy W_sindy, W_dec ----
        const float4* ws4 = (const float4*)W_sindy;
        float4* o1 = (float4*)(out + WS_OFF);
        for (int i = tid; i < (LDIM * LIB) / 4; i += 128) o1[i] = ws4[i];
        const float4* wd4 = (const float4*)W_dec;
        float4* o2 = (float4*)(out + WD_OFF);
        for (int i = tid; i < (FDIM * LDIM) / 4; i += 128) o2[i] = wd4[i];
        return;
    }

    const int g = bb / 9;
    const int r = bb - g * 9;

    if (r == 0) {
        // ---- role Y: y_hat, one thread per row ----
        float* s_Wt   = smem;              // [1016][16] transposed W_sindy
        float* s_feat = smem + LIB * LDIM; // [128][49] per-thread z/amp/ang

        for (int i = tid; i < LIB * LDIM; i += 128) {
            int l = i / LIB;
            int d = i - l * LIB;
            s_Wt[d * 16 + l] = W_sindy[i];
        }

        const int row = g * 128 + tid;
        float* f = s_feat + tid * 49;
        const float* zr = z     + (size_t)row * LDIM;
        const float* ar = g_amp + (size_t)row * LDIM;
        const float* gr = g_ang + (size_t)row * LDIM;
#pragma unroll
        for (int i = 0; i < 16; i++) {
            f[i]      = zr[i];
            f[16 + i] = ar[i];
            f[32 + i] = gr[i];
        }
        __syncthreads();

        float4 a0 = ((const float4*)b_sindy)[0];
        float4 a1 = ((const float4*)b_sindy)[1];
        float4 a2 = ((const float4*)b_sindy)[2];
        float4 a3 = ((const float4*)b_sindy)[3];
        const float4* w = (const float4*)s_Wt;

        // degree 1 (16 features)
#pragma unroll 1
        for (int i = 0; i < 16; i++) FEAT(f[i]);
        // degree 2 (136)
#pragma unroll 1
        for (int i = 0; i < 16; i++) {
            float zi = f[i];
#pragma unroll 1
            for (int j = i; j < 16; j++) FEAT(zi * f[j]);
        }
        // degree 3 (816)
#pragma unroll 1
        for (int i = 0; i < 16; i++) {
            float zi = f[i];
#pragma unroll 1
            for (int j = i; j < 16; j++) {
                float p = zi * f[j];
#pragma unroll 1
                for (int k = j; k < 16; k++) FEAT(p * f[k]);
            }
        }
        // z (16), amp (16), angle (16) — contiguous in f
#pragma unroll 1
        for (int i = 0; i < 48; i++) FEAT(f[i]);

        float4* yo = (float4*)(out + Y_OFF + (size_t)row * LDIM);
        yo[0] = a0; yo[1] = a1; yo[2] = a2; yo[3] = a3;
    } else if (r == 1) {
        // ---- role X: x_hat for rows [g*128, g*128+128), thread = f ----
        const float4* wd = (const float4*)W_dec;   // [128][4]
        float4 w0 = wd[tid * 4 + 0];
        float4 w1 = wd[tid * 4 + 1];
        float4 w2 = wd[tid * 4 + 2];
        float4 w3 = wd[tid * 4 + 3];
        float  bd = b_dec[tid];
        const int rbase = g * 128;
#pragma unroll 4
        for (int rr = 0; rr < 128; rr++) {
            const float4* zr = (const float4*)(z + (size_t)(rbase + rr) * LDIM);
            float4 z0 = __ldg(zr + 0), z1 = __ldg(zr + 1);
            float4 z2 = __ldg(zr + 2), z3 = __ldg(zr + 3);
            float v = bd;
            v = fmaf(z0.x, w0.x, v); v = fmaf(z0.y, w0.y, v);
            v = fmaf(z0.z, w0.z, v); v = fmaf(z0.w, w0.w, v);
            v = fmaf(z1.x, w1.x, v); v = fmaf(z1.y, w1.y, v);
            v = fmaf(z1.z, w1.z, v); v = fmaf(z1.w, w1.w, v);
            v = fmaf(z2.x, w2.x, v); v = fmaf(z2.y, w2.y, v);
            v = fmaf(z2.z, w2.z, v); v = fmaf(z2.w, w2.w, v);
            v = fmaf(z3.x, w3.x, v); v = fmaf(z3.y, w3.y, v);
            v = fmaf(z3.z, w3.z, v); v = fmaf(z3.w, w3.w, v);
            out[X_OFF + (size_t)(rbase + rr) * FDIM + tid] = v;
        }
    } else {
        // ---- role J: jac = W_enc tile repeated 32768x (streaming stores) ----
        float4* s_tile = (float4*)smem;           // 512 float4 = 8 KB
        const float4* we4 = (const float4*)W_enc;
        for (int i = tid; i < 512; i += 128) s_tile[i] = we4[i];
        __syncthreads();

        const int jb   = g * 7 + (r - 2);         // 0 .. 1791
        const int nJac = 1792;
        float4* jac4 = (float4*)(out + J_OFF);
        const size_t total  = (size_t)NROWS * LDIM * FDIM / 4;   // 16777216
        const size_t stride = (size_t)nJac * 128;
        for (size_t v = (size_t)jb * 128 + tid; v < total; v += stride) {
            float4 val = s_tile[v & 511];
            __stcs(&jac4[v], val);
        }
    }
}

// ---------------------------------------------------------------------------
extern "C" void kernel_launch(void* const* d_in, const int* in_sizes, int n_in,
                              void* d_out, int out_size)
{
    const float* x       = (const float*)d_in[0];
    const float* W_enc   = (const float*)d_in[1];
    const float* b_enc   = (const float*)d_in[2];
    const float* W_dec   = (const float*)d_in[3];
    const float* b_dec   = (const float*)d_in[4];
    const float* W_sindy = (const float*)d_in[5];
    const float* b_sindy = (const float*)d_in[6];
    float* out = (float*)d_out;

    float* z_out = out + Z_OFF;

    encoder_kernel<<<NROWS / 128, 128>>>(x, W_enc, b_enc, z_out);
    hilbert_kernel<<<BDIM * LDIM, 256>>>(z_out);

    static const int fused_smem = (LIB * LDIM + 128 * 49) * 4;   // 90112 B
    cudaFuncSetAttribute(fused_kernel,
                         cudaFuncAttributeMaxDynamicSharedMemorySize, fused_smem);
    fused_kernel<<<2305, 128, fused_smem>>>(W_enc, W_dec, b_dec,
                                            W_sindy, b_sindy, z_out, out);
}